// round 15
// baseline (speedup 1.0000x reference)
#include <cuda_runtime.h>

// bev_pool_v2 for B=8, N=6, D=88, fH=32, fW=88, C=80, BEV 1x128x128
// Inputs (metadata order): depth f32, feat f32, ranks_depth i32, ranks_feat i32, ranks_bev i32
// Output: (B, C, 1, 128, 128) f32
//
// TWO launches. Pass 1 bins points per BEV cell (atomic slot claim, depth
// value gathered into the entry, 4 pts/thread). Pass 2: one warp per 4 bins;
// entry list fetched with one coalesced load + shfl broadcast; feat row read
// as ONE LDG.128 per entry (lanes 0..19 own float4 chunks); fused transposed
// store into d_out. Segsum self-zeros g_count, folds overflow only in the
// ~0.2% of blocks that own an overflow entry (lane-parallel membership test),
// and the last block resets the global counters for the next graph replay.

#define CDIM   80
#define SPB    16384            // BEV_Z*BEV_Y*BEV_X per batch
#define BATCH  8
#define NBINS  (BATCH * SPB)    // 131072
#define CAP    32               // slots per bin (Poisson mean ~15.3; P(>32) ~ 3e-5)
#define OVFCAP 2048             // overflow safety list (expected usage: ~5-10)

__device__ int2  g_entries[NBINS * CAP];   // (depth_value_bits, ranks_feat), 32 MB
__device__ int   g_count[NBINS];           // static-init zero; re-zeroed by segsum
__device__ int   g_ovf_count;              // reset by segsum's last block
__device__ int   g_done;                   // segsum completion ticket
__device__ int4  g_ovf[OVFCAP];            // (rd, rf, rb, unused)

// Pass 1: scatter points into per-bin lists; 4 points per thread (int4 ranks).
__global__ void bin_kernel(const float* __restrict__ depth,
                           const int* __restrict__ ranks_depth,
                           const int* __restrict__ ranks_feat,
                           const int* __restrict__ ranks_bev,
                           int np) {
    int t = blockIdx.x * blockDim.x + threadIdx.x;
    int p0 = t * 4;
    if (p0 + 3 < np) {
        int4 rb4 = __ldg(reinterpret_cast<const int4*>(ranks_bev) + t);
        int4 rd4 = __ldg(reinterpret_cast<const int4*>(ranks_depth) + t);
        int4 rf4 = __ldg(reinterpret_cast<const int4*>(ranks_feat) + t);
        int rb[4] = {rb4.x, rb4.y, rb4.z, rb4.w};
        int rd[4] = {rd4.x, rd4.y, rd4.z, rd4.w};
        int rf[4] = {rf4.x, rf4.y, rf4.z, rf4.w};
        #pragma unroll
        for (int k = 0; k < 4; ++k) {
            int slot = atomicAdd(&g_count[rb[k]], 1);
            if (slot < CAP) {
                float d = __ldg(depth + rd[k]);
                g_entries[(size_t)rb[k] * CAP + slot] =
                    make_int2(__float_as_int(d), rf[k]);
            } else {
                int o = atomicAdd(&g_ovf_count, 1);
                if (o < OVFCAP) g_ovf[o] = make_int4(rd[k], rf[k], rb[k], 0);
            }
        }
    } else if (p0 < np) {
        for (int p = p0; p < np; ++p) {
            int rb = __ldg(ranks_bev + p);
            int rd = __ldg(ranks_depth + p);
            int rf = __ldg(ranks_feat + p);
            int slot = atomicAdd(&g_count[rb], 1);
            if (slot < CAP) {
                float d = __ldg(depth + rd);
                g_entries[(size_t)rb * CAP + slot] =
                    make_int2(__float_as_int(d), rf);
            } else {
                int o = atomicAdd(&g_ovf_count, 1);
                if (o < OVFCAP) g_ovf[o] = make_int4(rd, rf, rb, 0);
            }
        }
    }
}

// Pass 2: block = 32 consecutive bins of one batch; warp handles 4 bins.
__global__ void __launch_bounds__(256) segsum_fused_kernel(const float* __restrict__ depth,
                                                           const float* __restrict__ feat,
                                                           float* __restrict__ out) {
    __shared__ float tile[32][CDIM + 1];   // stride 81: odd -> conflict-free
    __shared__ int   s_ovf_n;
    __shared__ int   s_hit;
    int blk  = blockIdx.x;                 // NBINS/32 = 4096 blocks
    int b    = blk >> 9;                   // SPB/32 = 512 blocks per batch
    int s0   = (blk & 511) << 5;
    int base = b * SPB + s0;

    int warp = threadIdx.x >> 5;
    int lane = threadIdx.x & 31;
    bool act = (lane < 20);                // 20 float4 chunks cover C=80

    if (threadIdx.x == 0) {
        int n = g_ovf_count;
        s_ovf_n = (n > OVFCAP) ? OVFCAP : n;
        s_hit = 0;
    }

    #pragma unroll
    for (int j = 0; j < 4; ++j) {
        int local = warp * 4 + j;          // 0..31
        int bin   = base + local;

        int cnt = g_count[bin];            // uniform across warp
        if (lane == 0) g_count[bin] = 0;   // self-zero for next graph replay
        if (cnt > CAP) cnt = CAP;

        // One coalesced fetch of the whole entry list: lane i holds slot i.
        int2 my_e = make_int2(0, 0);
        if (lane < cnt)
            my_e = __ldg(&g_entries[(size_t)bin * CAP + lane]);

        float4 acc = make_float4(0.f, 0.f, 0.f, 0.f);

        int i = 0;
        for (; i + 1 < cnt; i += 2) {
            float d0 = __int_as_float(__shfl_sync(0xffffffffu, my_e.x, i));
            int   f0 = __shfl_sync(0xffffffffu, my_e.y, i);
            float d1 = __int_as_float(__shfl_sync(0xffffffffu, my_e.x, i + 1));
            int   f1 = __shfl_sync(0xffffffffu, my_e.y, i + 1);
            float4 v0 = make_float4(0.f, 0.f, 0.f, 0.f);
            float4 v1 = make_float4(0.f, 0.f, 0.f, 0.f);
            if (act) {
                v0 = __ldg(reinterpret_cast<const float4*>(feat + (size_t)f0 * CDIM) + lane);
                v1 = __ldg(reinterpret_cast<const float4*>(feat + (size_t)f1 * CDIM) + lane);
            }
            acc.x += d0 * v0.x + d1 * v1.x;
            acc.y += d0 * v0.y + d1 * v1.y;
            acc.z += d0 * v0.z + d1 * v1.z;
            acc.w += d0 * v0.w + d1 * v1.w;
        }
        if (i < cnt) {
            float d0 = __int_as_float(__shfl_sync(0xffffffffu, my_e.x, i));
            int   f0 = __shfl_sync(0xffffffffu, my_e.y, i);
            if (act) {
                float4 v0 = __ldg(reinterpret_cast<const float4*>(feat + (size_t)f0 * CDIM) + lane);
                acc.x += d0 * v0.x;
                acc.y += d0 * v0.y;
                acc.z += d0 * v0.z;
                acc.w += d0 * v0.w;
            }
        }

        if (act) {
            tile[local][lane * 4 + 0] = acc.x;
            tile[local][lane * 4 + 1] = acc.y;
            tile[local][lane * 4 + 2] = acc.z;
            tile[local][lane * 4 + 3] = acc.w;
        }
    }
    __syncthreads();

    // Cheap overflow membership test: only ~0.2% of blocks own an entry.
    int ovn = s_ovf_n;
    if (ovn > 0 && warp == 0) {
        bool hit = false;
        for (int o = lane; o < ovn; o += 32) {
            int rb = g_ovf[o].z;
            if (rb >= base && rb < base + 32) hit = true;
        }
        if (__any_sync(0xffffffffu, hit) && lane == 0) s_hit = 1;
    }
    __syncthreads();

    if (s_hit) {                           // rare: fold matching entries
        if (warp == 0) {
            for (int o = 0; o < ovn; ++o) {
                int4 e = g_ovf[o];
                int local = e.z - base;
                if (local >= 0 && local < 32) {
                    float d = __ldg(depth + e.x);
                    if (act) {
                        float4 v = __ldg(reinterpret_cast<const float4*>(
                            feat + (size_t)e.y * CDIM) + lane);
                        tile[local][lane * 4 + 0] += d * v.x;
                        tile[local][lane * 4 + 1] += d * v.y;
                        tile[local][lane * 4 + 2] += d * v.z;
                        tile[local][lane * 4 + 3] += d * v.w;
                    }
                }
            }
        }
        __syncthreads();
    }

    float* dst = out + (size_t)b * CDIM * SPB + s0;
    for (int k = threadIdx.x; k < 32 * CDIM; k += 256) {
        int c = k >> 5;
        int i = k & 31;
        dst[(size_t)c * SPB + i] = tile[i][c];   // 128B-coalesced per channel
    }

    // Last block to finish resets global counters for the next replay.
    if (threadIdx.x == 0) {
        if (atomicAdd(&g_done, 1) == (int)gridDim.x - 1) {
            g_done = 0;
            g_ovf_count = 0;
        }
    }
}

extern "C" void kernel_launch(void* const* d_in, const int* in_sizes, int n_in,
                              void* d_out, int out_size) {
    const float* depth       = (const float*)d_in[0];
    const float* feat        = (const float*)d_in[1];
    const int*   ranks_depth = (const int*)d_in[2];
    const int*   ranks_feat  = (const int*)d_in[3];
    const int*   ranks_bev   = (const int*)d_in[4];
    float*       out         = (float*)d_out;

    const int np = in_sizes[2];

    int nthreads = (np + 3) / 4;
    bin_kernel<<<(nthreads + 255) / 256, 256>>>(depth, ranks_depth, ranks_feat,
                                                ranks_bev, np);

    segsum_fused_kernel<<<NBINS / 32, 256>>>(depth, feat, out);  // writes all of out
}

// round 17
// speedup vs baseline: 1.1008x; 1.1008x over previous
#include <cuda_runtime.h>

// bev_pool_v2 for B=8, N=6, D=88, fH=32, fW=88, C=80, BEV 1x128x128
// Inputs (metadata order): depth f32, feat f32, ranks_depth i32, ranks_feat i32, ranks_bev i32
// Output: (B, C, 1, 128, 128) f32
//
// Proven R9 structure: pass 1 bins points per BEV cell (atomic slot claim,
// depth value gathered into the entry, 4 pts/thread). Pass 2: one warp per 4
// bins; entry list fetched with one coalesced load + shfl broadcast; feat row
// read as ONE LDG.128 per entry (lanes 0..19 own float4 chunks); fused
// transposed store into d_out. New: __launch_bounds__(256, 8) on segsum to
// lift occupancy (was 6 CTAs/SM @ 39 regs, 68% occ, latency-bound).

#define CDIM   80
#define SPB    16384            // BEV_Z*BEV_Y*BEV_X per batch
#define BATCH  8
#define NBINS  (BATCH * SPB)    // 131072
#define CAP    32               // slots per bin (Poisson mean ~15.3; P(>32) ~ 3e-5)
#define OVFCAP 2048             // overflow safety list (expected usage: ~5-10)

__device__ int2  g_entries[NBINS * CAP];   // (depth_value_bits, ranks_feat), 32 MB
__device__ int   g_count[NBINS];
__device__ int   g_ovf_count;
__device__ int4  g_ovf[OVFCAP];            // (rd, rf, rb, unused)

__global__ void zero_meta_kernel() {
    int i = blockIdx.x * blockDim.x + threadIdx.x;
    if (i < NBINS) g_count[i] = 0;
    if (i == 0) g_ovf_count = 0;
}

// Pass 1: scatter points into per-bin lists; 4 points per thread (int4 ranks).
__global__ void bin_kernel(const float* __restrict__ depth,
                           const int* __restrict__ ranks_depth,
                           const int* __restrict__ ranks_feat,
                           const int* __restrict__ ranks_bev,
                           int np) {
    int t = blockIdx.x * blockDim.x + threadIdx.x;
    int p0 = t * 4;
    if (p0 + 3 < np) {
        int4 rb4 = __ldg(reinterpret_cast<const int4*>(ranks_bev) + t);
        int4 rd4 = __ldg(reinterpret_cast<const int4*>(ranks_depth) + t);
        int4 rf4 = __ldg(reinterpret_cast<const int4*>(ranks_feat) + t);
        int rb[4] = {rb4.x, rb4.y, rb4.z, rb4.w};
        int rd[4] = {rd4.x, rd4.y, rd4.z, rd4.w};
        int rf[4] = {rf4.x, rf4.y, rf4.z, rf4.w};
        #pragma unroll
        for (int k = 0; k < 4; ++k) {
            int slot = atomicAdd(&g_count[rb[k]], 1);
            if (slot < CAP) {
                float d = __ldg(depth + rd[k]);
                g_entries[(size_t)rb[k] * CAP + slot] =
                    make_int2(__float_as_int(d), rf[k]);
            } else {
                int o = atomicAdd(&g_ovf_count, 1);
                if (o < OVFCAP) g_ovf[o] = make_int4(rd[k], rf[k], rb[k], 0);
            }
        }
    } else if (p0 < np) {
        for (int p = p0; p < np; ++p) {
            int rb = __ldg(ranks_bev + p);
            int rd = __ldg(ranks_depth + p);
            int rf = __ldg(ranks_feat + p);
            int slot = atomicAdd(&g_count[rb], 1);
            if (slot < CAP) {
                float d = __ldg(depth + rd);
                g_entries[(size_t)rb * CAP + slot] =
                    make_int2(__float_as_int(d), rf);
            } else {
                int o = atomicAdd(&g_ovf_count, 1);
                if (o < OVFCAP) g_ovf[o] = make_int4(rd, rf, rb, 0);
            }
        }
    }
}

// Pass 2: block = 32 consecutive bins of one batch; warp handles 4 bins.
// Lanes 0..19 each own a float4 chunk of the 80 channels -> whole feat row
// is ONE LDG.128 request per entry. min 8 CTAs/SM for latency hiding.
__global__ void __launch_bounds__(256, 8) segsum_fused_kernel(const float* __restrict__ feat,
                                                              float* __restrict__ out) {
    __shared__ float tile[32][CDIM + 1];   // stride 81: odd -> conflict-free
    int blk  = blockIdx.x;                 // NBINS/32 = 4096 blocks
    int b    = blk >> 9;                   // SPB/32 = 512 blocks per batch
    int s0   = (blk & 511) << 5;
    int base = b * SPB + s0;

    int warp = threadIdx.x >> 5;
    int lane = threadIdx.x & 31;
    bool act = (lane < 20);                // 20 float4 chunks cover C=80

    #pragma unroll
    for (int j = 0; j < 4; ++j) {
        int local = warp * 4 + j;          // 0..31
        int bin   = base + local;

        int cnt = g_count[bin];            // uniform across warp
        if (cnt > CAP) cnt = CAP;

        // One coalesced fetch of the whole entry list: lane i holds slot i.
        int2 my_e = make_int2(0, 0);
        if (lane < cnt)
            my_e = __ldg(&g_entries[(size_t)bin * CAP + lane]);

        float4 acc = make_float4(0.f, 0.f, 0.f, 0.f);

        int i = 0;
        for (; i + 1 < cnt; i += 2) {
            float d0 = __int_as_float(__shfl_sync(0xffffffffu, my_e.x, i));
            int   f0 = __shfl_sync(0xffffffffu, my_e.y, i);
            float d1 = __int_as_float(__shfl_sync(0xffffffffu, my_e.x, i + 1));
            int   f1 = __shfl_sync(0xffffffffu, my_e.y, i + 1);
            float4 v0 = make_float4(0.f, 0.f, 0.f, 0.f);
            float4 v1 = make_float4(0.f, 0.f, 0.f, 0.f);
            if (act) {
                v0 = __ldg(reinterpret_cast<const float4*>(feat + (size_t)f0 * CDIM) + lane);
                v1 = __ldg(reinterpret_cast<const float4*>(feat + (size_t)f1 * CDIM) + lane);
            }
            acc.x += d0 * v0.x + d1 * v1.x;
            acc.y += d0 * v0.y + d1 * v1.y;
            acc.z += d0 * v0.z + d1 * v1.z;
            acc.w += d0 * v0.w + d1 * v1.w;
        }
        if (i < cnt) {
            float d0 = __int_as_float(__shfl_sync(0xffffffffu, my_e.x, i));
            int   f0 = __shfl_sync(0xffffffffu, my_e.y, i);
            if (act) {
                float4 v0 = __ldg(reinterpret_cast<const float4*>(feat + (size_t)f0 * CDIM) + lane);
                acc.x += d0 * v0.x;
                acc.y += d0 * v0.y;
                acc.z += d0 * v0.z;
                acc.w += d0 * v0.w;
            }
        }

        if (act) {
            tile[local][lane * 4 + 0] = acc.x;
            tile[local][lane * 4 + 1] = acc.y;
            tile[local][lane * 4 + 2] = acc.z;
            tile[local][lane * 4 + 3] = acc.w;
        }
    }
    __syncthreads();

    float* dst = out + (size_t)b * CDIM * SPB + s0;
    for (int k = threadIdx.x; k < 32 * CDIM; k += 256) {
        int c = k >> 5;
        int i = k & 31;
        dst[(size_t)c * SPB + i] = tile[i][c];   // 128B-coalesced per channel
    }
}

// Pass 3: fold overflow entries (normally ~5-10) into the (B,C,S) output.
__global__ void overflow_kernel(const float* __restrict__ depth,
                                const float* __restrict__ feat,
                                float* __restrict__ out) {
    int n = g_ovf_count;
    if (n > OVFCAP) n = OVFCAP;
    int total = n * CDIM;
    for (int idx = blockIdx.x * blockDim.x + threadIdx.x; idx < total;
         idx += gridDim.x * blockDim.x) {
        int p = idx / CDIM;
        int c = idx - p * CDIM;
        int4 e = g_ovf[p];
        float d = __ldg(depth + e.x);
        float w = d * __ldg(feat + (size_t)e.y * CDIM + c);
        int b = e.z / SPB;
        int s = e.z - b * SPB;
        float* dst = out + (size_t)b * CDIM * SPB + (size_t)c * SPB + s;
        asm volatile("red.global.add.f32 [%0], %1;" :: "l"(dst), "f"(w) : "memory");
    }
}

extern "C" void kernel_launch(void* const* d_in, const int* in_sizes, int n_in,
                              void* d_out, int out_size) {
    const float* depth       = (const float*)d_in[0];
    const float* feat        = (const float*)d_in[1];
    const int*   ranks_depth = (const int*)d_in[2];
    const int*   ranks_feat  = (const int*)d_in[3];
    const int*   ranks_bev   = (const int*)d_in[4];
    float*       out         = (float*)d_out;

    const int np = in_sizes[2];

    zero_meta_kernel<<<(NBINS + 255) / 256, 256>>>();

    int nthreads = (np + 3) / 4;
    bin_kernel<<<(nthreads + 255) / 256, 256>>>(depth, ranks_depth, ranks_feat,
                                                ranks_bev, np);

    segsum_fused_kernel<<<NBINS / 32, 256>>>(feat, out);   // writes all of out

    overflow_kernel<<<32, 256>>>(depth, feat, out);
}